// round 13
// baseline (speedup 1.0000x reference)
#include <cuda_runtime.h>
#include <cuda_fp16.h>
#include <cstdint>

// Problem constants
#define NB 4
#define NL 2048
#define NH 8
#define NE 64
#define TENS_ELEMS (NB*NH*NL*NE)   // 4,194,304 halves per tensor
#define OP_OUT     (NB*NL*NH*NE)   // 4,194,304 floats per attention output

// Q is pre-scaled by 0.125 * log2(e) so S = Q K^T is the exp2 argument directly.
#define QSCALE 0.18033688f

// fp16 converted tensors, layout [w|m][b][h][l][e]
__device__ __align__(128) __half g_q[2][TENS_ELEMS];
__device__ __align__(128) __half g_k[2][TENS_ELEMS];
__device__ __align__(128) __half g_v[2][TENS_ELEMS];

// ======================= helpers =======================
__device__ __forceinline__ uint32_t smem_u32(const void* p) {
    uint32_t a;
    asm("{ .reg .u64 t; cvta.to.shared.u64 t, %1; cvt.u32.u64 %0, t; }" : "=r"(a) : "l"(p));
    return a;
}

#define CP_ASYNC16(dst, src) \
    asm volatile("cp.async.cg.shared.global [%0], [%1], 16;" :: "r"(dst), "l"(src))
#define CP_COMMIT()  asm volatile("cp.async.commit_group;" ::: "memory")
#define CP_WAIT(n)   asm volatile("cp.async.wait_group %0;" :: "n"(n) : "memory")

#define LDSM_X4(R0,R1,R2,R3,ADDR) \
    asm volatile("ldmatrix.sync.aligned.m8n8.x4.shared.b16 {%0,%1,%2,%3}, [%4];" \
        : "=r"(R0), "=r"(R1), "=r"(R2), "=r"(R3) : "r"(ADDR))
#define LDSM_X4_T(R0,R1,R2,R3,ADDR) \
    asm volatile("ldmatrix.sync.aligned.m8n8.x4.trans.shared.b16 {%0,%1,%2,%3}, [%4];" \
        : "=r"(R0), "=r"(R1), "=r"(R2), "=r"(R3) : "r"(ADDR))

__device__ __forceinline__ void mma16816(float* c, const uint32_t* a, uint32_t b0, uint32_t b1) {
    asm volatile(
        "mma.sync.aligned.m16n8k16.row.col.f32.f16.f16.f32 "
        "{%0,%1,%2,%3}, {%4,%5,%6,%7}, {%8,%9}, {%0,%1,%2,%3};"
        : "+f"(c[0]), "+f"(c[1]), "+f"(c[2]), "+f"(c[3])
        : "r"(a[0]), "r"(a[1]), "r"(a[2]), "r"(a[3]), "r"(b0), "r"(b1));
}

// ======================= pre-pass: fp32 [B,L,H,E] -> fp16 [B,H,L,E] =======================
__global__ void conv_kernel(const float* __restrict__ qw, const float* __restrict__ kw,
                            const float* __restrict__ vw, const float* __restrict__ qm,
                            const float* __restrict__ km, const float* __restrict__ vm) {
    int t = blockIdx.y;
    const float* src = (t == 0) ? qw : (t == 1) ? kw : (t == 2) ? vw
                     : (t == 3) ? qm : (t == 4) ? km : vm;
    __half* dst = (t == 0) ? g_q[0] : (t == 1) ? g_k[0] : (t == 2) ? g_v[0]
                : (t == 3) ? g_q[1] : (t == 4) ? g_k[1] : g_v[1];
    float sc = (t == 0 || t == 3) ? QSCALE : 1.0f;
    long idx = (long)blockIdx.x * blockDim.x + threadIdx.x;   // float4 index
    if (idx >= (long)TENS_ELEMS / 4) return;
    int e4 = (int)(idx & 15);
    long r = idx >> 4;
    int l = (int)(r & (NL - 1)); r >>= 11;
    int h = (int)(r & (NH - 1));
    int b = (int)(r >> 3);
    float4 v = reinterpret_cast<const float4*>(src)[(((long)b * NL + l) * NH + h) * (NE/4) + e4];
    __half2 h0 = __floats2half2_rn(v.x * sc, v.y * sc);
    __half2 h1 = __floats2half2_rn(v.z * sc, v.w * sc);
    uint2 pk = make_uint2(*reinterpret_cast<uint32_t*>(&h0), *reinterpret_cast<uint32_t*>(&h1));
    reinterpret_cast<uint2*>(dst)[(((long)b * NH + h) * NL + l) * (NE/4) + e4] = pk;
}

// ======================= main attention kernel =======================
// Tiles: BM=128 q-rows per CTA, BN=64 k-rows per iter, E=64.
// 4 warps x 32 q-rows. f32 accumulate. jj-fused inner loop (P transient, 8 regs).
// 4 CTAs/SM (128-reg cap) -> 16 warps/SM for latency hiding.
// SMEM: Q 16KB; K/V double buffer 2 x 16KB. Total 48KB + pad.
#define OFF_Q 0
#define OFF_K 16384
#define OFF_V 32768
#define SMEM_BYTES (49152 + 128)

__device__ __forceinline__ uint32_t sw_addr(uint32_t base, int row, int chunk) {
    return base + (uint32_t)(row * 128) + (uint32_t)((chunk ^ (row & 7)) << 4);
}

__device__ __forceinline__ void load_kv(uint32_t sb, const __half* kptr, const __half* vptr,
                                        int kt, int buf) {
    int tid = threadIdx.x;
    uint32_t kbase = sb + OFF_K + buf * 8192;
    uint32_t vbase = sb + OFF_V + buf * 8192;
    const __half* ks = kptr + (long)kt * 64 * NE;
    const __half* vs = vptr + (long)kt * 64 * NE;
#pragma unroll
    for (int j = 0; j < 4; j++) {
        int c = tid + j * 128;          // 512 chunks of 16B each for K and V
        int row = c >> 3, ch = c & 7;
        CP_ASYNC16(sw_addr(kbase, row, ch), ks + row * NE + ch * 8);
        CP_ASYNC16(sw_addr(vbase, row, ch), vs + row * NE + ch * 8);
    }
}

__global__ void __launch_bounds__(128, 4) attn_kernel(float* __restrict__ out) {
    extern __shared__ char smem_raw[];
    uint32_t sb = (smem_u32(smem_raw) + 127u) & ~127u;

    int x = blockIdx.x;
    int qt = x & 15, h = (x >> 4) & 7, b = (x >> 7) & 3, op = x >> 9;
    int qi = op & 1;
    int ki = (op == 1 || op == 2) ? 1 : 0;
    int bh = b * NH + h;
    const __half* qptr = g_q[qi] + (long)bh * NL * NE + (long)qt * 128 * NE;
    const __half* kptr = g_k[ki] + (long)bh * NL * NE;
    const __half* vptr = g_v[ki] + (long)bh * NL * NE;

    int tid = threadIdx.x;
    int lane = tid & 31;
    int warp = tid >> 5;
    int m0 = warp * 32;      // 32 q-rows per warp
    int lm = lane >> 3;      // ldmatrix sub-matrix index 0..3
    int lr = lane & 7;       // ldmatrix row within sub-matrix

    // --- stage Q (group 0) and K0/V0 (group 1) ---
    {
        uint32_t qb = sb + OFF_Q;
#pragma unroll
        for (int j = 0; j < 8; j++) {
            int c = tid + j * 128;        // 1024 chunks
            int row = c >> 3, ch = c & 7;
            CP_ASYNC16(sw_addr(qb, row, ch), qptr + row * NE + ch * 8);
        }
        CP_COMMIT();
        load_kv(sb, kptr, vptr, 0, 0);
        CP_COMMIT();
    }
    CP_WAIT(1);            // Q resident
    __syncthreads();

    // --- Q fragments: aQ[kc][mblk][0..3], resident across the mainloop ---
    uint32_t aQ[4][2][4];
#pragma unroll
    for (int kc = 0; kc < 4; kc++) {
#pragma unroll
        for (int mb = 0; mb < 2; mb++) {
            int row = m0 + mb * 16 + ((lm & 1) << 3) + lr;
            int ch  = 2 * kc + (lm >> 1);
            LDSM_X4(aQ[kc][mb][0], aQ[kc][mb][1], aQ[kc][mb][2], aQ[kc][mb][3],
                    sw_addr(sb + OFF_Q, row, ch));
        }
    }

    float o[2][8][4];            // f32 accumulator [mblk][d n8-block][frag]
#pragma unroll
    for (int mb = 0; mb < 2; mb++)
#pragma unroll
        for (int j = 0; j < 8; j++)
#pragma unroll
            for (int r = 0; r < 4; r++) o[mb][j][r] = 0.f;
    float rs[2][2] = {{0.f, 0.f}, {0.f, 0.f}};   // [mblk][rowA|rowB]

#pragma unroll 1
    for (int kt = 0; kt < 32; kt++) {
        int buf = kt & 1;
        CP_WAIT(0);
        __syncthreads();
        if (kt < 31) { load_kv(sb, kptr, vptr, kt + 1, buf ^ 1); CP_COMMIT(); }

        uint32_t kbase = sb + OFF_K + buf * 8192;
        uint32_t vbase = sb + OFF_V + buf * 8192;

        __half2 hsA[2], hsB[2];
        hsA[0] = hsA[1] = hsB[0] = hsB[1] = __float2half2_rn(0.f);

        // ---- fused per 16-key block jj: S (f32) -> exp2 -> PV (f32) ----
#pragma unroll
        for (int jj = 0; jj < 4; jj++) {
            float s[2][2][4];    // [mblk][nsub][frag], transient
#pragma unroll
            for (int mb = 0; mb < 2; mb++)
#pragma unroll
                for (int ns = 0; ns < 2; ns++)
#pragma unroll
                    for (int r = 0; r < 4; r++) s[mb][ns][r] = 0.f;
#pragma unroll
            for (int kc = 0; kc < 4; kc++) {
                int row = 16 * jj + ((lm >> 1) << 3) + lr;
                int ch  = 2 * kc + (lm & 1);
                uint32_t bk0, bk1, bk2, bk3;
                LDSM_X4(bk0, bk1, bk2, bk3, sw_addr(kbase, row, ch));
                mma16816(s[0][0], aQ[kc][0], bk0, bk1);
                mma16816(s[0][1], aQ[kc][0], bk2, bk3);
                mma16816(s[1][0], aQ[kc][1], bk0, bk1);
                mma16816(s[1][1], aQ[kc][1], bk2, bk3);
            }
            // exp2 -> fp16 P fragments (A-layout for PV), 8 regs transient
            uint32_t p[2][4];
#pragma unroll
            for (int mb = 0; mb < 2; mb++) {
                __half2 e0 = h2exp2(__floats2half2_rn(s[mb][0][0], s[mb][0][1]));
                __half2 e1 = h2exp2(__floats2half2_rn(s[mb][0][2], s[mb][0][3]));
                __half2 e2 = h2exp2(__floats2half2_rn(s[mb][1][0], s[mb][1][1]));
                __half2 e3 = h2exp2(__floats2half2_rn(s[mb][1][2], s[mb][1][3]));
                p[mb][0] = *reinterpret_cast<uint32_t*>(&e0);
                p[mb][1] = *reinterpret_cast<uint32_t*>(&e1);
                p[mb][2] = *reinterpret_cast<uint32_t*>(&e2);
                p[mb][3] = *reinterpret_cast<uint32_t*>(&e3);
                hsA[mb] = __hadd2(hsA[mb], __hadd2(e0, e2));
                hsB[mb] = __hadd2(hsB[mb], __hadd2(e1, e3));
            }
            // PV partial: V rows 16jj..16jj+15, all 64 d-columns
#pragma unroll
            for (int j2 = 0; j2 < 4; j2++) {
                int row = 16 * jj + ((lm & 1) << 3) + lr;
                int ch  = 2 * j2 + (lm >> 1);
                uint32_t bv0, bv1, bv2, bv3;
                LDSM_X4_T(bv0, bv1, bv2, bv3, sw_addr(vbase, row, ch));
                mma16816(o[0][2*j2],     p[0], bv0, bv1);
                mma16816(o[0][2*j2 + 1], p[0], bv2, bv3);
                mma16816(o[1][2*j2],     p[1], bv0, bv1);
                mma16816(o[1][2*j2 + 1], p[1], bv2, bv3);
            }
        }
#pragma unroll
        for (int mb = 0; mb < 2; mb++) {
            float2 fA = __half22float2(hsA[mb]);
            float2 fB = __half22float2(hsB[mb]);
            rs[mb][0] += fA.x + fA.y;
            rs[mb][1] += fB.x + fB.y;
        }
    }

    // ---- row-sum reduce across the 4 lanes sharing a row ----
#pragma unroll
    for (int mb = 0; mb < 2; mb++) {
#pragma unroll
        for (int rr = 0; rr < 2; rr++) {
            rs[mb][rr] += __shfl_xor_sync(0xffffffff, rs[mb][rr], 1);
            rs[mb][rr] += __shfl_xor_sync(0xffffffff, rs[mb][rr], 2);
        }
    }

    // ---- epilogue: out[op][b][l][h*64+d] ----
    int gid = lane >> 2, tig = lane & 3;
    long base = (long)op * OP_OUT + ((long)b * NL) * (NH * NE) + h * NE;
#pragma unroll
    for (int mb = 0; mb < 2; mb++) {
        float inv0 = 1.0f / rs[mb][0];
        float inv1 = 1.0f / rs[mb][1];
        int l0 = qt * 128 + m0 + mb * 16 + gid;
#pragma unroll
        for (int j = 0; j < 8; j++) {
            int d = 8 * j + 2 * tig;
            float2 v0 = make_float2(o[mb][j][0] * inv0, o[mb][j][1] * inv0);
            float2 v1 = make_float2(o[mb][j][2] * inv1, o[mb][j][3] * inv1);
            *reinterpret_cast<float2*>(out + base + (long)l0 * (NH * NE) + d) = v0;
            *reinterpret_cast<float2*>(out + base + (long)(l0 + 8) * (NH * NE) + d) = v1;
        }
    }
}

// ======================= launch =======================
extern "C" void kernel_launch(void* const* d_in, const int* in_sizes, int n_in,
                              void* d_out, int out_size) {
    const float* qw = (const float*)d_in[0];
    const float* kw = (const float*)d_in[1];
    const float* vw = (const float*)d_in[2];
    const float* qm = (const float*)d_in[3];
    const float* km = (const float*)d_in[4];
    const float* vm = (const float*)d_in[5];
    float* out = (float*)d_out;

    {
        dim3 g((TENS_ELEMS / 4 + 255) / 256, 6);
        conv_kernel<<<g, 256>>>(qw, kw, vw, qm, km, vm);
    }
    cudaFuncSetAttribute(attn_kernel, cudaFuncAttributeMaxDynamicSharedMemorySize, SMEM_BYTES);
    attn_kernel<<<2048, 128, SMEM_BYTES>>>(out);
}

// round 14
// speedup vs baseline: 1.2623x; 1.2623x over previous
#include <cuda_runtime.h>
#include <cuda_fp16.h>
#include <cstdint>

// Problem constants
#define NB 4
#define NL 2048
#define NH 8
#define NE 64
#define TENS_ELEMS (NB*NH*NL*NE)   // 4,194,304 halves per tensor
#define OP_OUT     (NB*NL*NH*NE)   // 4,194,304 floats per attention output

// Q is pre-scaled by 0.125 * log2(e) so S = Q K^T is the exp2 argument directly.
#define QSCALE 0.18033688f

// fp16 converted tensors, layout [w|m][b][h][l][e]
__device__ __align__(128) __half g_q[2][TENS_ELEMS];
__device__ __align__(128) __half g_k[2][TENS_ELEMS];
__device__ __align__(128) __half g_v[2][TENS_ELEMS];

// ======================= helpers =======================
__device__ __forceinline__ uint32_t smem_u32(const void* p) {
    uint32_t a;
    asm("{ .reg .u64 t; cvta.to.shared.u64 t, %1; cvt.u32.u64 %0, t; }" : "=r"(a) : "l"(p));
    return a;
}

#define CP_ASYNC16(dst, src) \
    asm volatile("cp.async.cg.shared.global [%0], [%1], 16;" :: "r"(dst), "l"(src))
#define CP_COMMIT()  asm volatile("cp.async.commit_group;" ::: "memory")
#define CP_WAIT(n)   asm volatile("cp.async.wait_group %0;" :: "n"(n) : "memory")

#define LDSM_X4(R0,R1,R2,R3,ADDR) \
    asm volatile("ldmatrix.sync.aligned.m8n8.x4.shared.b16 {%0,%1,%2,%3}, [%4];" \
        : "=r"(R0), "=r"(R1), "=r"(R2), "=r"(R3) : "r"(ADDR))
#define LDSM_X4_T(R0,R1,R2,R3,ADDR) \
    asm volatile("ldmatrix.sync.aligned.m8n8.x4.trans.shared.b16 {%0,%1,%2,%3}, [%4];" \
        : "=r"(R0), "=r"(R1), "=r"(R2), "=r"(R3) : "r"(ADDR))

// f32-accumulate HMMA (used for PV / O accumulation)
__device__ __forceinline__ void mma16816(float* c, const uint32_t* a, uint32_t b0, uint32_t b1) {
    asm volatile(
        "mma.sync.aligned.m16n8k16.row.col.f32.f16.f16.f32 "
        "{%0,%1,%2,%3}, {%4,%5,%6,%7}, {%8,%9}, {%0,%1,%2,%3};"
        : "+f"(c[0]), "+f"(c[1]), "+f"(c[2]), "+f"(c[3])
        : "r"(a[0]), "r"(a[1]), "r"(a[2]), "r"(a[3]), "r"(b0), "r"(b1));
}

// f16-accumulate HMMA (used only for transient S; same pipe rate, half the C regs)
__device__ __forceinline__ void mma16816_f16(uint32_t* c, const uint32_t* a,
                                             uint32_t b0, uint32_t b1) {
    asm volatile(
        "mma.sync.aligned.m16n8k16.row.col.f16.f16.f16.f16 "
        "{%0,%1}, {%2,%3,%4,%5}, {%6,%7}, {%0,%1};"
        : "+r"(c[0]), "+r"(c[1])
        : "r"(a[0]), "r"(a[1]), "r"(a[2]), "r"(a[3]), "r"(b0), "r"(b1));
}

// ======================= pre-pass: fp32 [B,L,H,E] -> fp16 [B,H,L,E] =======================
__global__ void conv_kernel(const float* __restrict__ qw, const float* __restrict__ kw,
                            const float* __restrict__ vw, const float* __restrict__ qm,
                            const float* __restrict__ km, const float* __restrict__ vm) {
    int t = blockIdx.y;
    const float* src = (t == 0) ? qw : (t == 1) ? kw : (t == 2) ? vw
                     : (t == 3) ? qm : (t == 4) ? km : vm;
    __half* dst = (t == 0) ? g_q[0] : (t == 1) ? g_k[0] : (t == 2) ? g_v[0]
                : (t == 3) ? g_q[1] : (t == 4) ? g_k[1] : g_v[1];
    float sc = (t == 0 || t == 3) ? QSCALE : 1.0f;
    long idx = (long)blockIdx.x * blockDim.x + threadIdx.x;   // float4 index
    if (idx >= (long)TENS_ELEMS / 4) return;
    int e4 = (int)(idx & 15);
    long r = idx >> 4;
    int l = (int)(r & (NL - 1)); r >>= 11;
    int h = (int)(r & (NH - 1));
    int b = (int)(r >> 3);
    float4 v = reinterpret_cast<const float4*>(src)[(((long)b * NL + l) * NH + h) * (NE/4) + e4];
    __half2 h0 = __floats2half2_rn(v.x * sc, v.y * sc);
    __half2 h1 = __floats2half2_rn(v.z * sc, v.w * sc);
    uint2 pk = make_uint2(*reinterpret_cast<uint32_t*>(&h0), *reinterpret_cast<uint32_t*>(&h1));
    reinterpret_cast<uint2*>(dst)[(((long)b * NH + h) * NL + l) * (NE/4) + e4] = pk;
}

// ======================= main attention kernel =======================
// R8 engine: BM=128, BN=64, 4 warps x 32 q-rows, coarse S-phase then PV-phase,
// double-buffered cp.async, 3 CTAs/SM @ 168 regs.
// New: S accumulated in f16 (transient, 8 regs) with exp2 applied IN PLACE on
// the C-fragments (f16 C-layout == A-layout needed by PV). O stays f32.
#define OFF_Q 0
#define OFF_K 16384
#define OFF_V 32768
#define SMEM_BYTES (49152 + 128)

__device__ __forceinline__ uint32_t sw_addr(uint32_t base, int row, int chunk) {
    return base + (uint32_t)(row * 128) + (uint32_t)((chunk ^ (row & 7)) << 4);
}

__device__ __forceinline__ void load_kv(uint32_t sb, const __half* kptr, const __half* vptr,
                                        int kt, int buf) {
    int tid = threadIdx.x;
    uint32_t kbase = sb + OFF_K + buf * 8192;
    uint32_t vbase = sb + OFF_V + buf * 8192;
    const __half* ks = kptr + (long)kt * 64 * NE;
    const __half* vs = vptr + (long)kt * 64 * NE;
#pragma unroll
    for (int j = 0; j < 4; j++) {
        int c = tid + j * 128;          // 512 chunks of 16B each for K and V
        int row = c >> 3, ch = c & 7;
        CP_ASYNC16(sw_addr(kbase, row, ch), ks + row * NE + ch * 8);
        CP_ASYNC16(sw_addr(vbase, row, ch), vs + row * NE + ch * 8);
    }
}

__global__ void __launch_bounds__(128, 3) attn_kernel(float* __restrict__ out) {
    extern __shared__ char smem_raw[];
    uint32_t sb = (smem_u32(smem_raw) + 127u) & ~127u;

    int x = blockIdx.x;
    int qt = x & 15, h = (x >> 4) & 7, b = (x >> 7) & 3, op = x >> 9;
    int qi = op & 1;
    int ki = (op == 1 || op == 2) ? 1 : 0;
    int bh = b * NH + h;
    const __half* qptr = g_q[qi] + (long)bh * NL * NE + (long)qt * 128 * NE;
    const __half* kptr = g_k[ki] + (long)bh * NL * NE;
    const __half* vptr = g_v[ki] + (long)bh * NL * NE;

    int tid = threadIdx.x;
    int lane = tid & 31;
    int warp = tid >> 5;
    int m0 = warp * 32;      // 32 q-rows per warp
    int lm = lane >> 3;      // ldmatrix sub-matrix index 0..3
    int lr = lane & 7;       // ldmatrix row within sub-matrix

    // --- stage Q (group 0) and K0/V0 (group 1) ---
    {
        uint32_t qb = sb + OFF_Q;
#pragma unroll
        for (int j = 0; j < 8; j++) {
            int c = tid + j * 128;        // 1024 chunks
            int row = c >> 3, ch = c & 7;
            CP_ASYNC16(sw_addr(qb, row, ch), qptr + row * NE + ch * 8);
        }
        CP_COMMIT();
        load_kv(sb, kptr, vptr, 0, 0);
        CP_COMMIT();
    }
    CP_WAIT(1);            // Q resident
    __syncthreads();

    // --- Q fragments: aQ[kc][mblk][0..3], resident across the mainloop ---
    uint32_t aQ[4][2][4];
#pragma unroll
    for (int kc = 0; kc < 4; kc++) {
#pragma unroll
        for (int mb = 0; mb < 2; mb++) {
            int row = m0 + mb * 16 + ((lm & 1) << 3) + lr;
            int ch  = 2 * kc + (lm >> 1);
            LDSM_X4(aQ[kc][mb][0], aQ[kc][mb][1], aQ[kc][mb][2], aQ[kc][mb][3],
                    sw_addr(sb + OFF_Q, row, ch));
        }
    }

    float o[2][8][4];            // f32 accumulator [mblk][d n8-block][frag]
#pragma unroll
    for (int mb = 0; mb < 2; mb++)
#pragma unroll
        for (int j = 0; j < 8; j++)
#pragma unroll
            for (int r = 0; r < 4; r++) o[mb][j][r] = 0.f;
    float rs[2][2] = {{0.f, 0.f}, {0.f, 0.f}};   // [mblk][rowA|rowB]

#pragma unroll 1
    for (int kt = 0; kt < 32; kt++) {
        int buf = kt & 1;
        CP_WAIT(0);
        __syncthreads();
        if (kt < 31) { load_kv(sb, kptr, vptr, kt + 1, buf ^ 1); CP_COMMIT(); }

        uint32_t kbase = sb + OFF_K + buf * 8192;
        uint32_t vbase = sb + OFF_V + buf * 8192;

        // ---- S-phase: S = Q K^T (f16 accum) -> exp2 in place -> P frags ----
        uint32_t p[4][2][4];     // [s-chunk jj][mblk][A-frag]
        __half2 hsA[2], hsB[2];
        hsA[0] = hsA[1] = hsB[0] = hsB[1] = __float2half2_rn(0.f);
#pragma unroll
        for (int jj = 0; jj < 4; jj++) {
            uint32_t s16[2][2][2];   // [mblk][nsub][creg], f16x2 accumulators (transient)
#pragma unroll
            for (int mb = 0; mb < 2; mb++)
#pragma unroll
                for (int ns = 0; ns < 2; ns++) { s16[mb][ns][0] = 0u; s16[mb][ns][1] = 0u; }
#pragma unroll
            for (int kc = 0; kc < 4; kc++) {
                int row = 16 * jj + ((lm >> 1) << 3) + lr;
                int ch  = 2 * kc + (lm & 1);
                uint32_t bk0, bk1, bk2, bk3;
                LDSM_X4(bk0, bk1, bk2, bk3, sw_addr(kbase, row, ch));
                mma16816_f16(s16[0][0], aQ[kc][0], bk0, bk1);
                mma16816_f16(s16[0][1], aQ[kc][0], bk2, bk3);
                mma16816_f16(s16[1][0], aQ[kc][1], bk0, bk1);
                mma16816_f16(s16[1][1], aQ[kc][1], bk2, bk3);
            }
            // exp2 directly on the f16 C-fragments; result IS the A-fragment for PV
#pragma unroll
            for (int mb = 0; mb < 2; mb++) {
                __half2 e0 = h2exp2(*reinterpret_cast<__half2*>(&s16[mb][0][0])); // row r,  cols n,n+1
                __half2 e1 = h2exp2(*reinterpret_cast<__half2*>(&s16[mb][0][1])); // row r+8
                __half2 e2 = h2exp2(*reinterpret_cast<__half2*>(&s16[mb][1][0])); // row r,  cols n+8,n+9
                __half2 e3 = h2exp2(*reinterpret_cast<__half2*>(&s16[mb][1][1])); // row r+8
                p[jj][mb][0] = *reinterpret_cast<uint32_t*>(&e0);
                p[jj][mb][1] = *reinterpret_cast<uint32_t*>(&e1);
                p[jj][mb][2] = *reinterpret_cast<uint32_t*>(&e2);
                p[jj][mb][3] = *reinterpret_cast<uint32_t*>(&e3);
                hsA[mb] = __hadd2(hsA[mb], __hadd2(e0, e2));
                hsB[mb] = __hadd2(hsB[mb], __hadd2(e1, e3));
            }
        }
#pragma unroll
        for (int mb = 0; mb < 2; mb++) {
            float2 fA = __half22float2(hsA[mb]);
            float2 fB = __half22float2(hsB[mb]);
            rs[mb][0] += fA.x + fA.y;
            rs[mb][1] += fB.x + fB.y;
        }

        // ---- PV-phase: O += P V (f32 accum) ----
#pragma unroll
        for (int kc = 0; kc < 4; kc++) {
#pragma unroll
            for (int jj = 0; jj < 4; jj++) {
                int row = 16 * kc + ((lm & 1) << 3) + lr;
                int ch  = 2 * jj + (lm >> 1);
                uint32_t bv0, bv1, bv2, bv3;
                LDSM_X4_T(bv0, bv1, bv2, bv3, sw_addr(vbase, row, ch));
                mma16816(o[0][2*jj],     p[kc][0], bv0, bv1);
                mma16816(o[0][2*jj + 1], p[kc][0], bv2, bv3);
                mma16816(o[1][2*jj],     p[kc][1], bv0, bv1);
                mma16816(o[1][2*jj + 1], p[kc][1], bv2, bv3);
            }
        }
    }

    // ---- row-sum reduce across the 4 lanes sharing a row ----
#pragma unroll
    for (int mb = 0; mb < 2; mb++) {
#pragma unroll
        for (int rr = 0; rr < 2; rr++) {
            rs[mb][rr] += __shfl_xor_sync(0xffffffff, rs[mb][rr], 1);
            rs[mb][rr] += __shfl_xor_sync(0xffffffff, rs[mb][rr], 2);
        }
    }

    // ---- epilogue: out[op][b][l][h*64+d] ----
    int gid = lane >> 2, tig = lane & 3;
    long base = (long)op * OP_OUT + ((long)b * NL) * (NH * NE) + h * NE;
#pragma unroll
    for (int mb = 0; mb < 2; mb++) {
        float inv0 = 1.0f / rs[mb][0];
        float inv1 = 1.0f / rs[mb][1];
        int l0 = qt * 128 + m0 + mb * 16 + gid;
#pragma unroll
        for (int j = 0; j < 8; j++) {
            int d = 8 * j + 2 * tig;
            float2 v0 = make_float2(o[mb][j][0] * inv0, o[mb][j][1] * inv0);
            float2 v1 = make_float2(o[mb][j][2] * inv1, o[mb][j][3] * inv1);
            *reinterpret_cast<float2*>(out + base + (long)l0 * (NH * NE) + d) = v0;
            *reinterpret_cast<float2*>(out + base + (long)(l0 + 8) * (NH * NE) + d) = v1;
        }
    }
}

// ======================= launch =======================
extern "C" void kernel_launch(void* const* d_in, const int* in_sizes, int n_in,
                              void* d_out, int out_size) {
    const float* qw = (const float*)d_in[0];
    const float* kw = (const float*)d_in[1];
    const float* vw = (const float*)d_in[2];
    const float* qm = (const float*)d_in[3];
    const float* km = (const float*)d_in[4];
    const float* vm = (const float*)d_in[5];
    float* out = (float*)d_out;

    {
        dim3 g((TENS_ELEMS / 4 + 255) / 256, 6);
        conv_kernel<<<g, 256>>>(qw, kw, vw, qm, km, vm);
    }
    cudaFuncSetAttribute(attn_kernel, cudaFuncAttributeMaxDynamicSharedMemorySize, SMEM_BYTES);
    attn_kernel<<<2048, 128, SMEM_BYTES>>>(out);
}

// round 16
// speedup vs baseline: 1.2963x; 1.0269x over previous
#include <cuda_runtime.h>
#include <cuda_fp16.h>
#include <cstdint>

// Problem constants
#define NB 4
#define NL 2048
#define NH 8
#define NE 64
#define TENS_ELEMS (NB*NH*NL*NE)   // 4,194,304 halves per tensor
#define OP_OUT     (NB*NL*NH*NE)   // 4,194,304 floats per attention output

// Q is scaled by 0.125 * log2(e) during in-kernel conversion: S is the exp2 arg.
#define QSCALE 0.18033688f

// fp16 converted K/V tensors, layout [w|m][b][h][l][e]  (Q converted in-kernel)
__device__ __align__(128) __half g_k[2][TENS_ELEMS];
__device__ __align__(128) __half g_v[2][TENS_ELEMS];

// ======================= helpers =======================
__device__ __forceinline__ uint32_t smem_u32(const void* p) {
    uint32_t a;
    asm("{ .reg .u64 t; cvta.to.shared.u64 t, %1; cvt.u32.u64 %0, t; }" : "=r"(a) : "l"(p));
    return a;
}

#define CP_ASYNC16(dst, src) \
    asm volatile("cp.async.cg.shared.global [%0], [%1], 16;" :: "r"(dst), "l"(src))
#define CP_COMMIT()  asm volatile("cp.async.commit_group;" ::: "memory")
#define CP_WAIT(n)   asm volatile("cp.async.wait_group %0;" :: "n"(n) : "memory")

#define LDSM_X4(R0,R1,R2,R3,ADDR) \
    asm volatile("ldmatrix.sync.aligned.m8n8.x4.shared.b16 {%0,%1,%2,%3}, [%4];" \
        : "=r"(R0), "=r"(R1), "=r"(R2), "=r"(R3) : "r"(ADDR))
#define LDSM_X4_T(R0,R1,R2,R3,ADDR) \
    asm volatile("ldmatrix.sync.aligned.m8n8.x4.trans.shared.b16 {%0,%1,%2,%3}, [%4];" \
        : "=r"(R0), "=r"(R1), "=r"(R2), "=r"(R3) : "r"(ADDR))

// VOLATILE + memory clobber: this load must not be reordered across
// cp.async.wait_group / __syncthreads (R15 bug: compiler hoisted it).
__device__ __forceinline__ float2 lds_f2(uint32_t a) {
    float2 r;
    asm volatile("ld.shared.v2.f32 {%0,%1}, [%2];"
                 : "=f"(r.x), "=f"(r.y) : "r"(a) : "memory");
    return r;
}
#define STS32(a, v) asm volatile("st.shared.b32 [%0], %1;" :: "r"(a), "r"(v) : "memory")

// f32-accumulate HMMA (PV / O accumulation)
__device__ __forceinline__ void mma16816(float* c, const uint32_t* a, uint32_t b0, uint32_t b1) {
    asm volatile(
        "mma.sync.aligned.m16n8k16.row.col.f32.f16.f16.f32 "
        "{%0,%1,%2,%3}, {%4,%5,%6,%7}, {%8,%9}, {%0,%1,%2,%3};"
        : "+f"(c[0]), "+f"(c[1]), "+f"(c[2]), "+f"(c[3])
        : "r"(a[0]), "r"(a[1]), "r"(a[2]), "r"(a[3]), "r"(b0), "r"(b1));
}

// f16-accumulate HMMA (transient S; same pipe rate, half the C regs)
__device__ __forceinline__ void mma16816_f16(uint32_t* c, const uint32_t* a,
                                             uint32_t b0, uint32_t b1) {
    asm volatile(
        "mma.sync.aligned.m16n8k16.row.col.f16.f16.f16.f16 "
        "{%0,%1}, {%2,%3,%4,%5}, {%6,%7}, {%0,%1};"
        : "+r"(c[0]), "+r"(c[1])
        : "r"(a[0]), "r"(a[1]), "r"(a[2]), "r"(a[3]), "r"(b0), "r"(b1));
}

// ======================= pre-pass: K/V only, fp32 [B,L,H,E] -> fp16 [B,H,L,E] =======================
__global__ void conv_kernel(const float* __restrict__ kw, const float* __restrict__ vw,
                            const float* __restrict__ km, const float* __restrict__ vm) {
    int t = blockIdx.y;
    const float* src = (t == 0) ? kw : (t == 1) ? vw : (t == 2) ? km : vm;
    __half* dst = (t == 0) ? g_k[0] : (t == 1) ? g_v[0] : (t == 2) ? g_k[1] : g_v[1];
    long idx = (long)blockIdx.x * blockDim.x + threadIdx.x;   // float4 index
    if (idx >= (long)TENS_ELEMS / 4) return;
    int e4 = (int)(idx & 15);
    long r = idx >> 4;
    int l = (int)(r & (NL - 1)); r >>= 11;
    int h = (int)(r & (NH - 1));
    int b = (int)(r >> 3);
    float4 v = reinterpret_cast<const float4*>(src)[(((long)b * NL + l) * NH + h) * (NE/4) + e4];
    __half2 h0 = __floats2half2_rn(v.x, v.y);
    __half2 h1 = __floats2half2_rn(v.z, v.w);
    uint2 pk = make_uint2(*reinterpret_cast<uint32_t*>(&h0), *reinterpret_cast<uint32_t*>(&h1));
    reinterpret_cast<uint2*>(dst)[(((long)b * NH + h) * NL + l) * (NE/4) + e4] = pk;
}

// ======================= main attention kernel =======================
// R14 engine: BM=128, BN=64, 4 warps x 32 q-rows, f16-accum transient S with
// in-place exp2, f32 O accumulator, 3 CTAs/SM.
// Q converted fp32->fp16 in the prologue (16KB staging, two 64-row passes);
// 4-buffer depth-2 cp.async pipeline for K/V.
// SMEM map (64KB):
//   [0,16K)      Q f32 staging (transient) -> later KV buffer for kt%4==2
//   [16K,32K)    Q fp16 swizzled (ldsm'd once) -> later KV buffer for kt%4==3
//   [32K,48K)    KV buffer kt%4==0   [48K,64K) KV buffer kt%4==1
#define OFF_QSTAGE 0
#define OFF_QF16   16384
#define SMEM_BYTES (65536 + 128)

__device__ __forceinline__ uint32_t sw_addr(uint32_t base, int row, int chunk) {
    return base + (uint32_t)(row * 128) + (uint32_t)((chunk ^ (row & 7)) << 4);
}

__device__ __forceinline__ uint32_t buf_base(uint32_t sb, int kt) {
    return sb + (uint32_t)(((kt & 2) ? 0 : 32768) + (kt & 1) * 16384);
}

__device__ __forceinline__ void load_kv(uint32_t sb, const __half* kptr, const __half* vptr,
                                        int kt) {
    int tid = threadIdx.x;
    uint32_t kbase = buf_base(sb, kt);
    uint32_t vbase = kbase + 8192;
    const __half* ks = kptr + (long)kt * 64 * NE;
    const __half* vs = vptr + (long)kt * 64 * NE;
#pragma unroll
    for (int j = 0; j < 4; j++) {
        int c = tid + j * 128;          // 512 chunks of 16B each for K and V
        int row = c >> 3, ch = c & 7;
        CP_ASYNC16(sw_addr(kbase, row, ch), ks + row * NE + ch * 8);
        CP_ASYNC16(sw_addr(vbase, row, ch), vs + row * NE + ch * 8);
    }
}

// stage 64 fp32 Q rows (row0..row0+63) into OFF_QSTAGE
__device__ __forceinline__ void stage_q_f32(uint32_t sb, const float* qsrc, int row0) {
    int tid = threadIdx.x;
#pragma unroll
    for (int j = 0; j < 8; j++) {
        int c = tid + j * 128;          // 1024 chunks: 64 rows x 16 chunks of 16B
        int row = c >> 4, ch = c & 15;
        CP_ASYNC16(sb + OFF_QSTAGE + (uint32_t)(row * 256 + ch * 16),
                   qsrc + (long)(row0 + row) * (NH * NE) + ch * 4);
    }
}

// convert staged 64 rows -> swizzled fp16 at rows row0..row0+63 of OFF_QF16
__device__ __forceinline__ void convert_q(uint32_t sb, int row0) {
    int tid = threadIdx.x;
#pragma unroll
    for (int j = 0; j < 16; j++) {
        int f = tid + j * 128;          // 2048 float2: 64 rows x 32
        int row = f >> 5, e2 = f & 31;
        float2 v = lds_f2(sb + OFF_QSTAGE + (uint32_t)(row * 256 + e2 * 8));
        __half2 hh = __floats2half2_rn(v.x * QSCALE, v.y * QSCALE);
        uint32_t addr = sw_addr(sb + OFF_QF16, row0 + row, e2 >> 2) + (uint32_t)((e2 & 3) * 4);
        STS32(addr, *reinterpret_cast<uint32_t*>(&hh));
    }
}

__global__ void __launch_bounds__(128, 3) attn_kernel(float* __restrict__ out,
                                                      const float* __restrict__ qw,
                                                      const float* __restrict__ qm) {
    extern __shared__ char smem_raw[];
    uint32_t sb = (smem_u32(smem_raw) + 127u) & ~127u;

    int x = blockIdx.x;
    int qt = x & 15, h = (x >> 4) & 7, b = (x >> 7) & 3, op = x >> 9;
    int qi = op & 1;
    int ki = (op == 1 || op == 2) ? 1 : 0;
    int bh = b * NH + h;
    const float* qsrc = (qi ? qm : qw) + ((long)(b * NL + qt * 128) * NH + h) * NE;
    const __half* kptr = g_k[ki] + (long)bh * NL * NE;
    const __half* vptr = g_v[ki] + (long)bh * NL * NE;

    int tid = threadIdx.x;
    int lane = tid & 31;
    int warp = tid >> 5;
    int m0 = warp * 32;      // 32 q-rows per warp
    int lm = lane >> 3;      // ldmatrix sub-matrix index 0..3
    int lr = lane & 7;       // ldmatrix row within sub-matrix

    // --- prologue: stage Q-lo (G0), KV0 (G1), KV1 (G2); convert Q in 2 passes ---
    stage_q_f32(sb, qsrc, 0);
    CP_COMMIT();                      // G0
    load_kv(sb, kptr, vptr, 0);
    CP_COMMIT();                      // G1  -> buffer 0 (32K)
    load_kv(sb, kptr, vptr, 1);
    CP_COMMIT();                      // G2  -> buffer 1 (48K)
    CP_WAIT(2);                       // Q-lo staged
    __syncthreads();
    convert_q(sb, 0);
    __syncthreads();                  // staging reusable
    stage_q_f32(sb, qsrc, 64);
    CP_COMMIT();                      // G3
    CP_WAIT(0);                       // everything (Q-hi + KV0/KV1) resident
    __syncthreads();
    convert_q(sb, 64);
    __syncthreads();

    // --- Q fragments: aQ[kc][mblk][0..3], resident across the mainloop ---
    uint32_t aQ[4][2][4];
#pragma unroll
    for (int kc = 0; kc < 4; kc++) {
#pragma unroll
        for (int mb = 0; mb < 2; mb++) {
            int row = m0 + mb * 16 + ((lm & 1) << 3) + lr;
            int ch  = 2 * kc + (lm >> 1);
            LDSM_X4(aQ[kc][mb][0], aQ[kc][mb][1], aQ[kc][mb][2], aQ[kc][mb][3],
                    sw_addr(sb + OFF_QF16, row, ch));
        }
    }

    float o[2][8][4];            // f32 accumulator [mblk][d n8-block][frag]
#pragma unroll
    for (int mb = 0; mb < 2; mb++)
#pragma unroll
        for (int j = 0; j < 8; j++)
#pragma unroll
            for (int r = 0; r < 4; r++) o[mb][j][r] = 0.f;
    float rs[2][2] = {{0.f, 0.f}, {0.f, 0.f}};   // [mblk][rowA|rowB]

#pragma unroll 1
    for (int kt = 0; kt < 32; kt++) {
        if (kt == 31) { CP_WAIT(0); } else { CP_WAIT(1); }   // tile kt resident
        __syncthreads();                                     // all warps past kt-1 reads
        if (kt + 2 < 32) { load_kv(sb, kptr, vptr, kt + 2); CP_COMMIT(); }

        uint32_t kbase = buf_base(sb, kt);
        uint32_t vbase = kbase + 8192;

        // ---- S-phase: S = Q K^T (f16 accum) -> exp2 in place -> P frags ----
        uint32_t p[4][2][4];     // [s-chunk jj][mblk][A-frag]
        __half2 hsA[2], hsB[2];
        hsA[0] = hsA[1] = hsB[0] = hsB[1] = __float2half2_rn(0.f);
#pragma unroll
        for (int jj = 0; jj < 4; jj++) {
            uint32_t s16[2][2][2];   // [mblk][nsub][creg], f16x2 accumulators (transient)
#pragma unroll
            for (int mb = 0; mb < 2; mb++)
#pragma unroll
                for (int ns = 0; ns < 2; ns++) { s16[mb][ns][0] = 0u; s16[mb][ns][1] = 0u; }
#pragma unroll
            for (int kc = 0; kc < 4; kc++) {
                int row = 16 * jj + ((lm >> 1) << 3) + lr;
                int ch  = 2 * kc + (lm & 1);
                uint32_t bk0, bk1, bk2, bk3;
                LDSM_X4(bk0, bk1, bk2, bk3, sw_addr(kbase, row, ch));
                mma16816_f16(s16[0][0], aQ[kc][0], bk0, bk1);
                mma16816_f16(s16[0][1], aQ[kc][0], bk2, bk3);
                mma16816_f16(s16[1][0], aQ[kc][1], bk0, bk1);
                mma16816_f16(s16[1][1], aQ[kc][1], bk2, bk3);
            }
            // exp2 directly on the f16 C-fragments; result IS the A-fragment for PV
#pragma unroll
            for (int mb = 0; mb < 2; mb++) {
                __half2 e0 = h2exp2(*reinterpret_cast<__half2*>(&s16[mb][0][0]));
                __half2 e1 = h2exp2(*reinterpret_cast<__half2*>(&s16[mb][0][1]));
                __half2 e2 = h2exp2(*reinterpret_cast<__half2*>(&s16[mb][1][0]));
                __half2 e3 = h2exp2(*reinterpret_cast<__half2*>(&s16[mb][1][1]));
                p[jj][mb][0] = *reinterpret_cast<uint32_t*>(&e0);
                p[jj][mb][1] = *reinterpret_cast<uint32_t*>(&e1);
                p[jj][mb][2] = *reinterpret_cast<uint32_t*>(&e2);
                p[jj][mb][3] = *reinterpret_cast<uint32_t*>(&e3);
                hsA[mb] = __hadd2(hsA[mb], __hadd2(e0, e2));
                hsB[mb] = __hadd2(hsB[mb], __hadd2(e1, e3));
            }
        }
#pragma unroll
        for (int mb = 0; mb < 2; mb++) {
            float2 fA = __half22float2(hsA[mb]);
            float2 fB = __half22float2(hsB[mb]);
            rs[mb][0] += fA.x + fA.y;
            rs[mb][1] += fB.x + fB.y;
        }

        // ---- PV-phase: O += P V (f32 accum) ----
#pragma unroll
        for (int kc = 0; kc < 4; kc++) {
#pragma unroll
            for (int jj = 0; jj < 4; jj++) {
                int row = 16 * kc + ((lm & 1) << 3) + lr;
                int ch  = 2 * jj + (lm >> 1);
                uint32_t bv0, bv1, bv2, bv3;
                LDSM_X4_T(bv0, bv1, bv2, bv3, sw_addr(vbase, row, ch));
                mma16816(o[0][2*jj],     p[kc][0], bv0, bv1);
                mma16816(o[0][2*jj + 1], p[kc][0], bv2, bv3);
                mma16816(o[1][2*jj],     p[kc][1], bv0, bv1);
                mma16816(o[1][2*jj + 1], p[kc][1], bv2, bv3);
            }
        }
    }

    // ---- row-sum reduce across the 4 lanes sharing a row ----
#pragma unroll
    for (int mb = 0; mb < 2; mb++) {
#pragma unroll
        for (int rr = 0; rr < 2; rr++) {
            rs[mb][rr] += __shfl_xor_sync(0xffffffff, rs[mb][rr], 1);
            rs[mb][rr] += __shfl_xor_sync(0xffffffff, rs[mb][rr], 2);
        }
    }

    // ---- epilogue: out[op][b][l][h*64+d] ----
    int gid = lane >> 2, tig = lane & 3;
    long base = (long)op * OP_OUT + ((long)b * NL) * (NH * NE) + h * NE;
#pragma unroll
    for (int mb = 0; mb < 2; mb++) {
        float inv0 = 1.0f / rs[mb][0];
        float inv1 = 1.0f / rs[mb][1];
        int l0 = qt * 128 + m0 + mb * 16 + gid;
#pragma unroll
        for (int j = 0; j < 8; j++) {
            int d = 8 * j + 2 * tig;
            float2 v0 = make_float2(o[mb][j][0] * inv0, o[mb][j][1] * inv0);
            float2 v1 = make_float2(o[mb][j][2] * inv1, o[mb][j][3] * inv1);
            *reinterpret_cast<float2*>(out + base + (long)l0 * (NH * NE) + d) = v0;
            *reinterpret_cast<float2*>(out + base + (long)(l0 + 8) * (NH * NE) + d) = v1;
        }
    }
}

// ======================= launch =======================
extern "C" void kernel_launch(void* const* d_in, const int* in_sizes, int n_in,
                              void* d_out, int out_size) {
    const float* qw = (const float*)d_in[0];
    const float* kw = (const float*)d_in[1];
    const float* vw = (const float*)d_in[2];
    const float* qm = (const float*)d_in[3];
    const float* km = (const float*)d_in[4];
    const float* vm = (const float*)d_in[5];
    float* out = (float*)d_out;

    {
        dim3 g((TENS_ELEMS / 4 + 255) / 256, 4);
        conv_kernel<<<g, 256>>>(kw, vw, km, vm);
    }
    cudaFuncSetAttribute(attn_kernel, cudaFuncAttributeMaxDynamicSharedMemorySize, SMEM_BYTES);
    attn_kernel<<<2048, 128, SMEM_BYTES>>>(out, qw, qm);
}